// round 10
// baseline (speedup 1.0000x reference)
#include <cuda_runtime.h>

#define NQ     1224
#define NSTEPS 50
#define NB     1024
#define NROWS  (NB * (NSTEPS - 1))     // 50176 (b, t) pairs, t in [1, 49]
#define NV     (NQ / 4)                // 306 uint4 per one-hot half
#define WARPS_PER_BLOCK 8
#define NBLOCKS 1184                   // 148 SMs x 8 blocks -> exactly 1 wave at 256 thr
#define TOTAL_WARPS (NBLOCKS * WARPS_PER_BLOCK)   // 9472

// Allocation-free scratch: per-block partials + completion counter.
// Every partial slot is written unconditionally each run; the counter uses
// atomicInc wrap semantics to self-reset to 0, so graph replay is clean.
__device__ float    g_partials[NBLOCKS];
__device__ unsigned g_counter = 0;

// Scan one (b,t) row of batch. The 2448-wide row is an exact one-hot: one
// 1.0f in either the "correct" half [0,NQ) or the "incorrect" half [NQ,2NQ).
// Both halves are scanned in lockstep as uint4 (1.0f has nonzero bits, 0.0f
// is all-zero); depth-1 prefetch overlaps the next chunk's loads with the
// current chunk's ballot. At most ONE lane in the warp can hit. Returns the
// BCE term on the winner lane, 0 elsewhere; a fully-zero row returns 0,
// matching the reference's mask. pred values are in (0,1) by construction,
// so the reference's p > 0 mask is always satisfied on a hit.
__device__ __forceinline__ float scan_row(
    const uint4* __restrict__ row1,
    const uint4* __restrict__ row2,
    const float* __restrict__ pred_row,
    int lane)
{
    const uint4 z = make_uint4(0u, 0u, 0u, 0u);
    int v = lane;
    uint4 f0 = z, s0 = z;
    if (v < NV) { f0 = __ldg(row1 + v); s0 = __ldg(row2 + v); }

    #pragma unroll 1
    for (int c = 0; c < 10; ++c) {
        // Prefetch next chunk before the ballot consumes this one.
        int vn = v + 32;
        uint4 f1 = z, s1 = z;
        if (vn < NV) { f1 = __ldg(row1 + vn); s1 = __ldg(row2 + vn); }

        unsigned orf = f0.x | f0.y | f0.z | f0.w;
        unsigned ors = s0.x | s0.y | s0.z | s0.w;
        unsigned m = __ballot_sync(0xffffffffu, (orf | ors) != 0u);
        if (m) {
            float r = 0.0f;
            if ((orf | ors) != 0u) {
                uint4 act = orf ? f0 : s0;
                int idx = act.x ? 0 : (act.y ? 1 : (act.z ? 2 : 3));
                float p = __ldg(pred_row + (4 * v + idx));
                r = orf ? logf(p) : logf(1.0f - p);
            }
            return r;   // ballot result is warp-uniform: all lanes leave together
        }
        f0 = f1; s0 = s1; v = vn;
    }
    return 0.0f;
}

// Persistent-warp kernel: each warp independently processes rows
// warp, warp+TOTAL_WARPS, ... with lane-local accumulation. No block-level
// synchronization until the final reduction, so early-exit rows immediately
// free the warp for its next row (kills the max-of-8-geometrics straggler
// inflation seen at DRAM=57%).
__global__ __launch_bounds__(256) void dkt_loss_kernel(
    const float* __restrict__ pred,
    const float* __restrict__ batch,
    float* __restrict__ out)
{
    const int warp = blockIdx.x * WARPS_PER_BLOCK + (threadIdx.x >> 5);
    const int lane = threadIdx.x & 31;

    float contrib = 0.0f;

    for (int row = warp; row < NROWS; row += TOTAL_WARPS) {
        int b = row / (NSTEPS - 1);
        int t = row - b * (NSTEPS - 1) + 1;   // 1..49

        const uint4* row1 = (const uint4*)(batch + ((size_t)b * NSTEPS + t) * (size_t)(2 * NQ));
        const uint4* row2 = row1 + NV;
        const float* pred_row = pred + ((size_t)b * NSTEPS + (t - 1)) * (size_t)NQ;

        contrib += scan_row(row1, row2, pred_row, lane);
    }

    // Warp reduction, then block reduction.
    #pragma unroll
    for (int o = 16; o; o >>= 1)
        contrib += __shfl_xor_sync(0xffffffffu, contrib, o);

    __shared__ float wsum[WARPS_PER_BLOCK];
    __shared__ bool  is_last;
    if (lane == 0) wsum[threadIdx.x >> 5] = contrib;
    __syncthreads();

    if (threadIdx.x == 0) {
        float blocksum = 0.0f;
        #pragma unroll
        for (int i = 0; i < WARPS_PER_BLOCK; i++) blocksum += wsum[i];
        g_partials[blockIdx.x] = blocksum;
        __threadfence();
        unsigned old = atomicInc(&g_counter, (unsigned)(gridDim.x - 1));
        is_last = (old == gridDim.x - 1);
    }
    __syncthreads();

    // Last block reduces the 1184 partials in double and writes the output.
    if (is_last) {
        double s = 0.0;
        for (int i = threadIdx.x; i < NBLOCKS; i += blockDim.x)
            s += (double)g_partials[i];

        #pragma unroll
        for (int o = 16; o; o >>= 1)
            s += __shfl_xor_sync(0xffffffffu, s, o);

        __shared__ double dsum[WARPS_PER_BLOCK];
        if (lane == 0) dsum[threadIdx.x >> 5] = s;
        __syncthreads();

        if (threadIdx.x == 0) {
            double total = 0.0;
            #pragma unroll
            for (int i = 0; i < WARPS_PER_BLOCK; i++) total += dsum[i];
            out[0] = (float)(-total);
        }
    }
}

extern "C" void kernel_launch(void* const* d_in, const int* in_sizes, int n_in,
                              void* d_out, int out_size)
{
    // Identify inputs by element count (robust to metadata ordering):
    // pred  = 1024*50*1224 = 62,668,800
    // batch = 1024*50*2448 = 125,337,600
    const float* pred;
    const float* batch;
    if (in_sizes[0] == NB * NSTEPS * NQ) {
        pred  = (const float*)d_in[0];
        batch = (const float*)d_in[1];
    } else {
        pred  = (const float*)d_in[1];
        batch = (const float*)d_in[0];
    }

    dkt_loss_kernel<<<NBLOCKS, 256>>>(pred, batch, (float*)d_out);
}

// round 11
// speedup vs baseline: 1.1366x; 1.1366x over previous
#include <cuda_runtime.h>

#define NQ     1224
#define NSTEPS 50
#define NB     1024
#define NROWS  (NB * (NSTEPS - 1))   // 50176 (b, t) pairs, t in [1, 49]
#define NV     (NQ / 4)              // 306 uint4 per one-hot half
#define WARPS_PER_BLOCK 8
#define NBLOCKS (NROWS / WARPS_PER_BLOCK)   // 6272, exact

// Allocation-free scratch. g_sum is reset to 0.0 by the last finishing block
// each run, so graph replays start clean. The counter self-resets via
// atomicInc wrap semantics.
__device__ double   g_sum = 0.0;
__device__ unsigned g_counter = 0;

// One warp per (b, t) row of `batch` (t >= 1), contiguous warp->row mapping
// (consecutive warps on an SM scan adjacent 9.8KB regions -> good DRAM
// locality; this mapping measured 5.3 TB/s in round 8). The 2448-wide row is
// an exact one-hot: a single 1.0f in either the "correct" half [0,NQ) or the
// "incorrect" half [NQ,2NQ). Scan both halves in lockstep as uint4 (1.0f has
// nonzero bits); early-exit on the first nonzero via ballot. Hit column q =
// question index; which half = label a. Gather pred[b,t-1,q] and accumulate
// the BCE term. pred is in (0,1) by construction, so the reference's `p > 0`
// mask is always satisfied on a hit; an all-zero row contributes 0, matching
// the masked reference.
__global__ __launch_bounds__(256) void dkt_loss_kernel(
    const float* __restrict__ pred,
    const float* __restrict__ batch,
    float* __restrict__ out)
{
    const int warp = blockIdx.x * WARPS_PER_BLOCK + (threadIdx.x >> 5);
    const int lane = threadIdx.x & 31;

    int b = warp / (NSTEPS - 1);
    int t = warp - b * (NSTEPS - 1) + 1;   // 1..49

    const uint4* row1 = (const uint4*)(batch + ((size_t)b * NSTEPS + t) * (size_t)(2 * NQ));
    const uint4* row2 = row1 + NV;
    const float* pred_row = pred + ((size_t)b * NSTEPS + (t - 1)) * (size_t)NQ;

    float contrib = 0.0f;

    #pragma unroll 1
    for (int base = 0; base < NV; base += 32) {
        int v = base + lane;
        uint4 f = make_uint4(0u, 0u, 0u, 0u);
        uint4 s = make_uint4(0u, 0u, 0u, 0u);
        if (v < NV) {
            f = __ldg(row1 + v);
            s = __ldg(row2 + v);
        }

        unsigned orf = f.x | f.y | f.z | f.w;
        unsigned ors = s.x | s.y | s.z | s.w;
        unsigned m = __ballot_sync(0xffffffffu, (orf | ors) != 0u);
        if (m) {
            if ((orf | ors) != 0u) {     // at most one lane: the one-hot owner
                uint4 act = orf ? f : s;
                int idx = act.x ? 0 : (act.y ? 1 : (act.z ? 2 : 3));
                float p = __ldg(pred_row + (4 * v + idx));
                contrib = orf ? logf(p) : logf(1.0f - p);
            }
            break;   // ballot result is warp-uniform: no divergence hazard
        }
    }

    // Warp reduction (at most one lane is nonzero, but reduce anyway).
    #pragma unroll
    for (int o = 16; o; o >>= 1)
        contrib += __shfl_xor_sync(0xffffffffu, contrib, o);

    __shared__ float wsum[WARPS_PER_BLOCK];
    if (lane == 0) wsum[threadIdx.x >> 5] = contrib;
    __syncthreads();

    if (threadIdx.x == 0) {
        float blocksum = 0.0f;
        #pragma unroll
        for (int i = 0; i < WARPS_PER_BLOCK; i++) blocksum += wsum[i];

        // Accumulate in double; the add overlaps the remaining scan work of
        // other blocks, so the finalize tail is essentially free.
        atomicAdd(&g_sum, (double)blocksum);
        __threadfence();
        unsigned old = atomicInc(&g_counter, (unsigned)(gridDim.x - 1));
        if (old == gridDim.x - 1) {
            // Last block: everyone's atomicAdd is globally visible (fenced
            // before their counter increment). Publish and reset for replay.
            double total = g_sum;
            out[0] = (float)(-total);
            g_sum = 0.0;
        }
    }
}

extern "C" void kernel_launch(void* const* d_in, const int* in_sizes, int n_in,
                              void* d_out, int out_size)
{
    // Identify inputs by element count (robust to metadata ordering):
    // pred  = 1024*50*1224 = 62,668,800
    // batch = 1024*50*2448 = 125,337,600
    const float* pred;
    const float* batch;
    if (in_sizes[0] == NB * NSTEPS * NQ) {
        pred  = (const float*)d_in[0];
        batch = (const float*)d_in[1];
    } else {
        pred  = (const float*)d_in[1];
        batch = (const float*)d_in[0];
    }

    dkt_loss_kernel<<<NBLOCKS, 256>>>(pred, batch, (float*)d_out);
}